// round 8
// baseline (speedup 1.0000x reference)
#include <cuda_runtime.h>
#include <math_constants.h>

#define HH 256
#define WW 256
#define NIMG 512          // B*C = 8*64
#define CCH 64
#define HWSZ 65536        // 256*256
#define SEGROWS 16
#define NSEG 16           // 256 / SEGROWS

// Scratch (static device globals — no runtime allocation)
__device__ float g_cmax32[NIMG * HH * 32];    // per-(row, lane=8col) max of dst

__device__ __forceinline__ int rrow(int r) {
    return r < 0 ? -r : (r >= HH ? 2*HH - 2 - r : r);
}

// clamp dynamic local-array index into [0,4] — prevents speculative
// out-of-frame LDL when ptxas flattens the border branches into selects
#define CL(i) (min(max((int)(i), 0), 4))

// ---------------------------------------------------------------------------
// Pass A: Harris response R -> per-lane chunk maxes of the 3x3-dilated field
// (dst itself never materialized), out=x copy fused into the stencil row
// loads. One warp per (image, 16-row segment); lane owns 8 columns.
// All FP contractions pinned with explicit fmaf so the apply path can
// recompute dst bit-identically.
// ---------------------------------------------------------------------------

// Load x row r (reflect-101). If the REQUESTED row lies in this segment,
// also store it to out (each segment row passes through here exactly once).
#define LOAD_XROW(r, dst_)  do {                                              \
    int rq__ = (r);                                                           \
    int rr__ = (rq__ < 0) ? -rq__ : ((rq__ >= HH) ? (2*HH - 2 - rq__) : rq__);\
    const float4* p__ = reinterpret_cast<const float4*>(xim + rr__ * WW + cb);\
    float4 q0__ = p__[0], q1__ = p__[1];                                      \
    dst_[0]=q0__.x; dst_[1]=q0__.y; dst_[2]=q0__.z; dst_[3]=q0__.w;           \
    dst_[4]=q1__.x; dst_[5]=q1__.y; dst_[6]=q1__.z; dst_[7]=q1__.w;           \
    if ((unsigned)(rq__ - r0) < (unsigned)SEGROWS) {                          \
        float4* po__ = reinterpret_cast<float4*>(oim + rq__ * WW + cb);       \
        po__[0] = q0__; po__[1] = q1__;                                       \
    }                                                                         \
} while(0)

#define COMPUTE_DD(row, AX, AXY, AY) do {                                     \
    float xc__[8]; LOAD_XROW((row)+1, xc__);                                  \
    float u__[8], v__[8];                                                     \
    _Pragma("unroll")                                                         \
    for (int i=0;i<8;i++){ u__[i] = fmaf(2.0f, xb[i], xa[i]) + xc__[i];       \
                           v__[i] = xc__[i] - xa[i]; }                        \
    float uL__ = __shfl_up_sync(0xffffffffu, u__[7], 1);                      \
    float uR__ = __shfl_down_sync(0xffffffffu, u__[0], 1);                    \
    float vL__ = __shfl_up_sync(0xffffffffu, v__[7], 1);                      \
    float vR__ = __shfl_down_sync(0xffffffffu, v__[0], 1);                    \
    if (lane == 0)  { uL__ = u__[1]; vL__ = v__[1]; }                         \
    if (lane == 31) { uR__ = u__[6]; vR__ = v__[6]; }                         \
    _Pragma("unroll")                                                         \
    for (int i=0;i<8;i++){                                                    \
        float um1__ = (i==0)? uL__ : u__[i-1];                                \
        float up1__ = (i==7)? uR__ : u__[i+1];                                \
        float vm1__ = (i==0)? vL__ : v__[i-1];                                \
        float vp1__ = (i==7)? vR__ : v__[i+1];                                \
        float dx__ = (up1__ - um1__) * SC;                                    \
        float dy__ = (fmaf(2.0f, v__[i], vm1__) + vp1__) * SC;                \
        AX[i] = dx__*dx__; AXY[i] = dx__*dy__; AY[i] = dy__*dy__;             \
    }                                                                         \
    _Pragma("unroll")                                                         \
    for (int i=0;i<8;i++){ xa[i] = xb[i]; xb[i] = xc__[i]; }                  \
} while(0)

// Horizontal sums + R + per-lane row max h + emit chunkmax row q = PV-1.
#define EMIT_P(PV) do {                                                       \
    float xxL__ = __shfl_up_sync(0xffffffffu, sxx[7],1);                      \
    float xxR__ = __shfl_down_sync(0xffffffffu, sxx[0],1);                    \
    float xyL__ = __shfl_up_sync(0xffffffffu, sxy[7],1);                      \
    float xyR__ = __shfl_down_sync(0xffffffffu, sxy[0],1);                    \
    float yyL__ = __shfl_up_sync(0xffffffffu, syy[7],1);                      \
    float yyR__ = __shfl_down_sync(0xffffffffu, syy[0],1);                    \
    if (lane==0){  xxL__=sxx[1]; xyL__=sxy[1]; yyL__=syy[1]; }                \
    if (lane==31){ xxR__=sxx[6]; xyR__=sxy[6]; yyR__=syy[6]; }                \
    float Rv__[8];                                                            \
    _Pragma("unroll")                                                         \
    for (int i=0;i<8;i++){                                                    \
        float ixx = (((i==0)?xxL__:sxx[i-1]) + sxx[i]) + ((i==7)?xxR__:sxx[i+1]);\
        float ixy = (((i==0)?xyL__:sxy[i-1]) + sxy[i]) + ((i==7)?xyR__:sxy[i+1]);\
        float iyy = (((i==0)?yyL__:syy[i-1]) + syy[i]) + ((i==7)?yyR__:syy[i+1]);\
        float t1__ = ixy * ixy;                                               \
        float det__ = fmaf(ixx, iyy, -t1__);                                  \
        float tr__  = ixx + iyy;                                              \
        float t2__ = tr__ * tr__;                                             \
        Rv__[i] = fmaf(-0.04f, t2__, det__);                                  \
    }                                                                         \
    float RL__ = __shfl_up_sync(0xffffffffu, Rv__[7],1);                      \
    float RR__ = __shfl_down_sync(0xffffffffu, Rv__[0],1);                    \
    if (lane==0)  RL__ = -CUDART_INF_F;                                       \
    if (lane==31) RR__ = -CUDART_INF_F;                                       \
    float hc__ = fmaxf(RL__, RR__);                                           \
    _Pragma("unroll")                                                         \
    for (int i=0;i<8;i++) hc__ = fmaxf(hc__, Rv__[i]);                        \
    int q__ = (PV) - 1;                                                       \
    if (q__ >= r0) {                                                          \
        float cm__ = fmaxf(fmaxf(hb, ha), hc__);                              \
        g_cmax32[((img<<8)+q__)*32 + lane] = cm__;                            \
    }                                                                         \
    hb = ha; ha = hc__;                                                       \
} while(0)

__global__ void __launch_bounds__(32, 16) harris_kernel(const float* __restrict__ x,
                                                        float* __restrict__ out) {
    const int img  = blockIdx.x >> 4;
    const int seg  = blockIdx.x & (NSEG - 1);
    const int lane = threadIdx.x;
    const int cb   = lane * 8;
    const float* __restrict__ xim = x + (size_t)img * HWSZ;
    float* __restrict__ oim = out + (size_t)img * HWSZ;

    const int r0 = seg * SEGROWS;
    const int r1 = r0 + SEGROWS;

    const float SC = (1.0f / 12.0f);   // SOBEL_SCALE
    float xa[8], xb[8];
    float p2x[8], p2y[8], p2z[8];      // P2 = dd(p-1)+dd(p)   (xx,xy,yy)
    float cx[8],  cy[8],  cz[8];       // C  = dd(p)
    float ha = -CUDART_INF_F, hb = -CUDART_INF_F;  // h(p-1), h(p-2)

    int pstart;
    if (r0 == 0) {
        LOAD_XROW(-1, xa);
        LOAD_XROW(0,  xb);
        COMPUTE_DD(0, cx, cy, cz);
#pragma unroll
        for (int i=0;i<8;i++){ p2x[i]=cx[i]+cx[i]; p2y[i]=cy[i]+cy[i]; p2z[i]=cz[i]+cz[i]; }
        // peeled p == 0 iteration (emits q=-1: nothing; shifts ha/hb)
        {
            float nx[8], ny[8], nz[8];
            COMPUTE_DD(1, nx, ny, nz);
            float sxx[8], sxy[8], syy[8];
#pragma unroll
            for (int i=0;i<8;i++){ sxx[i]=fmaf(2.0f, nx[i], cx[i]);
                                   sxy[i]=fmaf(2.0f, ny[i], cy[i]);
                                   syy[i]=fmaf(2.0f, nz[i], cz[i]); }
#pragma unroll
            for (int i=0;i<8;i++){ p2x[i]=cx[i]+nx[i]; cx[i]=nx[i];
                                   p2y[i]=cy[i]+ny[i]; cy[i]=ny[i];
                                   p2z[i]=cz[i]+nz[i]; cz[i]=nz[i]; }
            EMIT_P(0);
        }
        pstart = 1;
    } else {
        float d1x[8], d1y[8], d1z[8];
        LOAD_XROW(r0 - 3, xa);
        LOAD_XROW(r0 - 2, xb);
        COMPUTE_DD(r0 - 2, d1x, d1y, d1z);
        COMPUTE_DD(r0 - 1, cx, cy, cz);
#pragma unroll
        for (int i=0;i<8;i++){ p2x[i]=d1x[i]+cx[i]; p2y[i]=d1y[i]+cy[i]; p2z[i]=d1z[i]+cz[i]; }
        pstart = r0 - 1;
    }

    const int pend = (r1 == HH) ? (HH - 1) : (r1 + 1);
#pragma unroll 2
    for (int p = pstart; p < pend; ++p) {
        float nx[8], ny[8], nz[8];
        COMPUTE_DD(p+1, nx, ny, nz);
        float sxx[8], sxy[8], syy[8];
#pragma unroll
        for (int i=0;i<8;i++){ sxx[i]=p2x[i]+nx[i];
                               sxy[i]=p2y[i]+ny[i];
                               syy[i]=p2z[i]+nz[i]; }
#pragma unroll
        for (int i=0;i<8;i++){ p2x[i]=cx[i]+nx[i]; cx[i]=nx[i];
                               p2y[i]=cy[i]+ny[i]; cy[i]=ny[i];
                               p2z[i]=cz[i]+nz[i]; cz[i]=nz[i]; }
        EMIT_P(p);
    }

    if (r1 == HH) {
        // peel p = 255: vertical sum = dd(255) + 2*(p2-dd(255)) (= +2*dd(254))
        float sxx[8], sxy[8], syy[8];
#pragma unroll
        for (int i=0;i<8;i++){
            sxx[i] = fmaf(2.0f, p2x[i] - cx[i], cx[i]);
            sxy[i] = fmaf(2.0f, p2y[i] - cy[i], cy[i]);
            syy[i] = fmaf(2.0f, p2z[i] - cz[i], cz[i]);
        }
        EMIT_P(255);
        // bottom image row: chunkmax(255) = max(h(254), h(255))
        g_cmax32[((img<<8)+(HH-1))*32 + lane] = fmaxf(hb, ha);
    }
}

// ---------------------------------------------------------------------------
// Detect + apply: ONE block per image (512 blocks x 256 threads). Thread t
// owns row t: 8 coalesced float4 loads of cmax (cached in regs), block
// reduction gives the image max directly (same value set as dst max ->
// bit-identical threshold). Flagged chunks go to a shared list (4096 cap =
// total chunks, cannot overflow); the block's 8 warps then process them:
// recompute dst bit-identical to pass A, lane-parallel conv1x1, overwrite out.
// ---------------------------------------------------------------------------
__global__ void __launch_bounds__(256) detect_apply_kernel(
        const float* __restrict__ x, const float* __restrict__ wt,
        const float* __restrict__ bias, float* __restrict__ out) {
    __shared__ float sred[256];
    __shared__ int   slist[4096];
    __shared__ int   scount;
    const int img = blockIdx.x;
    const int tid = threadIdx.x;
    if (tid == 0) scount = 0;

    // load this row's 32 lane-maxes (8 float4, MLP 8)
    float4 v[8];
    const float4* cb4 = reinterpret_cast<const float4*>(
        g_cmax32 + (size_t)img * (HH * 32) + tid * 32);
#pragma unroll
    for (int j = 0; j < 8; ++j) v[j] = cb4[j];

    float rmax = fmaxf(fmaxf(v[0].x, v[0].y), fmaxf(v[0].z, v[0].w));
#pragma unroll
    for (int j = 1; j < 8; ++j)
        rmax = fmaxf(rmax, fmaxf(fmaxf(v[j].x, v[j].y), fmaxf(v[j].z, v[j].w)));
    sred[tid] = rmax;
    __syncthreads();
    for (int s = 128; s > 0; s >>= 1) {
        if (tid < s) sred[tid] = fmaxf(sred[tid], sred[tid + s]);
        __syncthreads();
    }
    const float thr = 0.7f * sred[0];   // THRESH_FRAC * image max

    // flag chunks (chunk 2j = lanes 4j,4j+1; chunk 2j+1 = lanes 4j+2,4j+3)
#pragma unroll
    for (int j = 0; j < 8; ++j) {
        if (fmaxf(v[j].x, v[j].y) >= thr) slist[atomicAdd(&scount, 1)] = (tid << 4) + 2*j;
        if (fmaxf(v[j].z, v[j].w) >= thr) slist[atomicAdd(&scount, 1)] = (tid << 4) + 2*j + 1;
    }
    __syncthreads();
    const int n = scount;
    if (n == 0) return;

    const int wid  = tid >> 5;
    const int lane = tid & 31;
    const float SC = (1.0f / 12.0f);
    const float* __restrict__ xim = x + (size_t)img * HWSZ;

    for (int li = wid; li < n; li += 8) {
        int rc  = slist[li];
        int q   = rc >> 4;
        int c0  = (rc & 15) << 4;

        int c  = c0 - 2 + lane;                 // field column
        int cc = (c < 0) ? -c : (c >= WW ? 2*WW - 2 - c : c);
        int cL = (cc == 0) ? 1 : cc - 1;        // reflect-101 col for x loads
        int cR = (cc == WW-1) ? WW-2 : cc + 1;

        int dlo = q - 2 < 0 ? 0 : q - 2;

        // Upfront parallel loads: 7 rows x 3 cols (independent -> MLP 21).
        float xr0[7], xr1[7], xr2[7];
#pragma unroll
        for (int j = 0; j < 7; ++j) {
            int rj = rrow(dlo - 1 + j) * WW;
            xr0[j] = xim[rj + cL];
            xr1[j] = xim[rj + cc];
            xr2[j] = xim[rj + cR];
        }
        float xq = xim[q * WW + cc];            // x at (q, cc) for the mask

        float ddx[5], ddxy[5], ddy2[5];
#pragma unroll
        for (int k = 0; k < 5; ++k) {           // d = dlo + k (k>span unused)
            float uL = fmaf(2.0f, xr0[k+1], xr0[k]) + xr0[k+2];
            float uR = fmaf(2.0f, xr2[k+1], xr2[k]) + xr2[k+2];
            float vL = xr0[k+2] - xr0[k];
            float vC = xr1[k+2] - xr1[k];
            float vR = xr2[k+2] - xr2[k];
            float dx = (uR - uL) * SC;
            float dy = (fmaf(2.0f, vC, vL) + vR) * SC;
            ddx[k]  = dx * dx;
            ddxy[k] = dx * dy;
            ddy2[k] = dy * dy;
        }

        float dstv = -CUDART_INF_F;
        for (int rr = q - 1; rr <= q + 1; ++rr) {
            if (rr < 0 || rr > HH - 1) continue;
            float sxx, sxy, syy;
            if (rr == 0) {
                sxx = fmaf(2.0f, ddx[CL(1 - dlo)],  ddx[CL(0 - dlo)]);
                sxy = fmaf(2.0f, ddxy[CL(1 - dlo)], ddxy[CL(0 - dlo)]);
                syy = fmaf(2.0f, ddy2[CL(1 - dlo)], ddy2[CL(0 - dlo)]);
            } else if (rr == HH - 1) {
                float p2a = ddx[CL(254 - dlo)]  + ddx[CL(255 - dlo)];
                float p2b = ddxy[CL(254 - dlo)] + ddxy[CL(255 - dlo)];
                float p2c = ddy2[CL(254 - dlo)] + ddy2[CL(255 - dlo)];
                sxx = fmaf(2.0f, p2a - ddx[CL(255 - dlo)],  ddx[CL(255 - dlo)]);
                sxy = fmaf(2.0f, p2b - ddxy[CL(255 - dlo)], ddxy[CL(255 - dlo)]);
                syy = fmaf(2.0f, p2c - ddy2[CL(255 - dlo)], ddy2[CL(255 - dlo)]);
            } else {
                sxx = (ddx[CL(rr - 1 - dlo)]  + ddx[CL(rr - dlo)])  + ddx[CL(rr + 1 - dlo)];
                sxy = (ddxy[CL(rr - 1 - dlo)] + ddxy[CL(rr - dlo)]) + ddxy[CL(rr + 1 - dlo)];
                syy = (ddy2[CL(rr - 1 - dlo)] + ddy2[CL(rr - dlo)]) + ddy2[CL(rr + 1 - dlo)];
            }
            float xxm = __shfl_up_sync(0xffffffffu, sxx, 1);
            float xxp = __shfl_down_sync(0xffffffffu, sxx, 1);
            float xym = __shfl_up_sync(0xffffffffu, sxy, 1);
            float xyp = __shfl_down_sync(0xffffffffu, sxy, 1);
            float yym = __shfl_up_sync(0xffffffffu, syy, 1);
            float yyp = __shfl_down_sync(0xffffffffu, syy, 1);
            float ixx = (xxm + sxx) + xxp;
            float ixy = (xym + sxy) + xyp;
            float iyy = (yym + syy) + yyp;
            float t1 = ixy * ixy;
            float det = fmaf(ixx, iyy, -t1);
            float tr  = ixx + iyy;
            float t2 = tr * tr;
            float Rv = fmaf(-0.04f, t2, det);
            if (c < 0 || c > WW - 1) Rv = -CUDART_INF_F;   // dilation clips
            float Rm = __shfl_up_sync(0xffffffffu, Rv, 1);
            float Rp = __shfl_down_sync(0xffffffffu, Rv, 1);
            float mm = fmaxf(fmaxf(Rm, Rv), Rp);
            dstv = fmaxf(dstv, mm);
        }

        bool flg = (lane >= 2) && (lane < 18) && (dstv >= thr);
        unsigned bal = __ballot_sync(0xffffffffu, flg);
        if (bal) {
            int b   = img >> 6;
            int cch = img & 63;
            float w0 = wt[(cch << 6) + 2*lane];
            float w1 = wt[(cch << 6) + 2*lane + 1];
            float bi = bias[cch];
            const float* xbase = x + (size_t)(b << 6) * HWSZ;
            while (bal) {
                int lp = __ffs(bal) - 1; bal &= bal - 1;
                int pix = (q << 8) + c0 + lp - 2;
                float xv0 = xbase[(size_t)(2*lane)     * HWSZ + pix];
                float xv1 = xbase[(size_t)(2*lane + 1) * HWSZ + pix];
                float acc = fmaf(w0, xv0, w1 * xv1);
#pragma unroll
                for (int o = 16; o; o >>= 1)
                    acc += __shfl_xor_sync(0xffffffffu, acc, o);
                if (lane == lp) {
                    float y = fmaxf(acc + bi, 0.0f);
                    float mask = (dstv > thr) ? 1.0f : xq;   // tie keeps pixel
                    out[(size_t)img * HWSZ + pix] = fmaf(mask, y, xq);
                }
            }
        }
    }
}

extern "C" void kernel_launch(void* const* d_in, const int* in_sizes, int n_in,
                              void* d_out, int out_size) {
    const float* x = (const float*)d_in[0];
    const float* w = (const float*)d_in[1];
    const float* b = (const float*)d_in[2];
    float* out = (float*)d_out;
    harris_kernel<<<NIMG * NSEG, 32>>>(x, out);
    detect_apply_kernel<<<NIMG, 256>>>(x, w, b, out);
}

// round 9
// speedup vs baseline: 1.3122x; 1.3122x over previous
#include <cuda_runtime.h>
#include <math_constants.h>

#define HH 256
#define WW 256
#define NIMG 512          // B*C = 8*64
#define CCH 64
#define HWSZ 65536        // 256*256
#define SEGROWS 16
#define NSEG 16           // 256 / SEGROWS
#define NCHUNK (NIMG * HH * 16)

// Scratch (static device globals — no runtime allocation)
__device__ float g_cmax32[NIMG * HH * 32];    // per-(row, lane=8col) max of dst
__device__ float g_segmax[NIMG * NSEG];       // per-segment max of dst
__device__ float g_tmax[NIMG];                // 0.7 * per-image max
__device__ int   g_list[NCHUNK];              // flagged chunk ids
__device__ int   g_count;

__device__ __forceinline__ int rrow(int r) {
    return r < 0 ? -r : (r >= HH ? 2*HH - 2 - r : r);
}

// clamp dynamic local-array index into [0,4] — prevents speculative
// out-of-frame LDL when ptxas flattens the border branches into selects
#define CL(i) (min(max((int)(i), 0), 4))

// ---------------------------------------------------------------------------
// Pass A: Harris response R -> per-lane chunk maxes of the 3x3-dilated field
// (dst itself never materialized), segment maxes, out=x copy fused into the
// stencil row loads. One warp per (image, 16-row segment); lane owns 8 cols.
// All FP contractions pinned with explicit fmaf so the apply path can
// recompute dst bit-identically.
// ---------------------------------------------------------------------------

// Load x row r (reflect-101). If the REQUESTED row lies in this segment,
// also store it to out (each segment row passes through here exactly once).
#define LOAD_XROW(r, dst_)  do {                                              \
    int rq__ = (r);                                                           \
    int rr__ = (rq__ < 0) ? -rq__ : ((rq__ >= HH) ? (2*HH - 2 - rq__) : rq__);\
    const float4* p__ = reinterpret_cast<const float4*>(xim + rr__ * WW + cb);\
    float4 q0__ = p__[0], q1__ = p__[1];                                      \
    dst_[0]=q0__.x; dst_[1]=q0__.y; dst_[2]=q0__.z; dst_[3]=q0__.w;           \
    dst_[4]=q1__.x; dst_[5]=q1__.y; dst_[6]=q1__.z; dst_[7]=q1__.w;           \
    if ((unsigned)(rq__ - r0) < (unsigned)SEGROWS) {                          \
        float4* po__ = reinterpret_cast<float4*>(oim + rq__ * WW + cb);       \
        po__[0] = q0__; po__[1] = q1__;                                       \
    }                                                                         \
} while(0)

#define COMPUTE_DD(row, AX, AXY, AY) do {                                     \
    float xc__[8]; LOAD_XROW((row)+1, xc__);                                  \
    float u__[8], v__[8];                                                     \
    _Pragma("unroll")                                                         \
    for (int i=0;i<8;i++){ u__[i] = fmaf(2.0f, xb[i], xa[i]) + xc__[i];       \
                           v__[i] = xc__[i] - xa[i]; }                        \
    float uL__ = __shfl_up_sync(0xffffffffu, u__[7], 1);                      \
    float uR__ = __shfl_down_sync(0xffffffffu, u__[0], 1);                    \
    float vL__ = __shfl_up_sync(0xffffffffu, v__[7], 1);                      \
    float vR__ = __shfl_down_sync(0xffffffffu, v__[0], 1);                    \
    if (lane == 0)  { uL__ = u__[1]; vL__ = v__[1]; }                         \
    if (lane == 31) { uR__ = u__[6]; vR__ = v__[6]; }                         \
    _Pragma("unroll")                                                         \
    for (int i=0;i<8;i++){                                                    \
        float um1__ = (i==0)? uL__ : u__[i-1];                                \
        float up1__ = (i==7)? uR__ : u__[i+1];                                \
        float vm1__ = (i==0)? vL__ : v__[i-1];                                \
        float vp1__ = (i==7)? vR__ : v__[i+1];                                \
        float dx__ = (up1__ - um1__) * SC;                                    \
        float dy__ = (fmaf(2.0f, v__[i], vm1__) + vp1__) * SC;                \
        AX[i] = dx__*dx__; AXY[i] = dx__*dy__; AY[i] = dy__*dy__;             \
    }                                                                         \
    _Pragma("unroll")                                                         \
    for (int i=0;i<8;i++){ xa[i] = xb[i]; xb[i] = xc__[i]; }                  \
} while(0)

// Horizontal sums + R + per-lane row max h + emit chunkmax row q = PV-1.
#define EMIT_P(PV) do {                                                       \
    float xxL__ = __shfl_up_sync(0xffffffffu, sxx[7],1);                      \
    float xxR__ = __shfl_down_sync(0xffffffffu, sxx[0],1);                    \
    float xyL__ = __shfl_up_sync(0xffffffffu, sxy[7],1);                      \
    float xyR__ = __shfl_down_sync(0xffffffffu, sxy[0],1);                    \
    float yyL__ = __shfl_up_sync(0xffffffffu, syy[7],1);                      \
    float yyR__ = __shfl_down_sync(0xffffffffu, syy[0],1);                    \
    if (lane==0){  xxL__=sxx[1]; xyL__=sxy[1]; yyL__=syy[1]; }                \
    if (lane==31){ xxR__=sxx[6]; xyR__=sxy[6]; yyR__=syy[6]; }                \
    float Rv__[8];                                                            \
    _Pragma("unroll")                                                         \
    for (int i=0;i<8;i++){                                                    \
        float ixx = (((i==0)?xxL__:sxx[i-1]) + sxx[i]) + ((i==7)?xxR__:sxx[i+1]);\
        float ixy = (((i==0)?xyL__:sxy[i-1]) + sxy[i]) + ((i==7)?xyR__:sxy[i+1]);\
        float iyy = (((i==0)?yyL__:syy[i-1]) + syy[i]) + ((i==7)?yyR__:syy[i+1]);\
        float t1__ = ixy * ixy;                                               \
        float det__ = fmaf(ixx, iyy, -t1__);                                  \
        float tr__  = ixx + iyy;                                              \
        float t2__ = tr__ * tr__;                                             \
        Rv__[i] = fmaf(-0.04f, t2__, det__);                                  \
    }                                                                         \
    float RL__ = __shfl_up_sync(0xffffffffu, Rv__[7],1);                      \
    float RR__ = __shfl_down_sync(0xffffffffu, Rv__[0],1);                    \
    if (lane==0)  RL__ = -CUDART_INF_F;                                       \
    if (lane==31) RR__ = -CUDART_INF_F;                                       \
    float hc__ = fmaxf(RL__, RR__);                                           \
    _Pragma("unroll")                                                         \
    for (int i=0;i<8;i++) hc__ = fmaxf(hc__, Rv__[i]);                        \
    int q__ = (PV) - 1;                                                       \
    if (q__ >= r0) {                                                          \
        float cm__ = fmaxf(fmaxf(hb, ha), hc__);                              \
        lmax = fmaxf(lmax, cm__);                                             \
        g_cmax32[((img<<8)+q__)*32 + lane] = cm__;                            \
    }                                                                         \
    hb = ha; ha = hc__;                                                       \
} while(0)

__global__ void __launch_bounds__(32, 16) harris_kernel(const float* __restrict__ x,
                                                        float* __restrict__ out) {
    if (blockIdx.x == 0 && threadIdx.x == 0) g_count = 0;   // reset list
    const int img  = blockIdx.x >> 4;
    const int seg  = blockIdx.x & (NSEG - 1);
    const int lane = threadIdx.x;
    const int cb   = lane * 8;
    const float* __restrict__ xim = x + (size_t)img * HWSZ;
    float* __restrict__ oim = out + (size_t)img * HWSZ;

    const int r0 = seg * SEGROWS;
    const int r1 = r0 + SEGROWS;

    const float SC = (1.0f / 12.0f);   // SOBEL_SCALE
    float xa[8], xb[8];
    float p2x[8], p2y[8], p2z[8];      // P2 = dd(p-1)+dd(p)   (xx,xy,yy)
    float cx[8],  cy[8],  cz[8];       // C  = dd(p)
    float ha = -CUDART_INF_F, hb = -CUDART_INF_F;  // h(p-1), h(p-2)
    float lmax = -CUDART_INF_F;

    int pstart;
    if (r0 == 0) {
        LOAD_XROW(-1, xa);
        LOAD_XROW(0,  xb);
        COMPUTE_DD(0, cx, cy, cz);
#pragma unroll
        for (int i=0;i<8;i++){ p2x[i]=cx[i]+cx[i]; p2y[i]=cy[i]+cy[i]; p2z[i]=cz[i]+cz[i]; }
        // peeled p == 0 iteration (emits q=-1: nothing; shifts ha/hb)
        {
            float nx[8], ny[8], nz[8];
            COMPUTE_DD(1, nx, ny, nz);
            float sxx[8], sxy[8], syy[8];
#pragma unroll
            for (int i=0;i<8;i++){ sxx[i]=fmaf(2.0f, nx[i], cx[i]);
                                   sxy[i]=fmaf(2.0f, ny[i], cy[i]);
                                   syy[i]=fmaf(2.0f, nz[i], cz[i]); }
#pragma unroll
            for (int i=0;i<8;i++){ p2x[i]=cx[i]+nx[i]; cx[i]=nx[i];
                                   p2y[i]=cy[i]+ny[i]; cy[i]=ny[i];
                                   p2z[i]=cz[i]+nz[i]; cz[i]=nz[i]; }
            EMIT_P(0);
        }
        pstart = 1;
    } else {
        float d1x[8], d1y[8], d1z[8];
        LOAD_XROW(r0 - 3, xa);
        LOAD_XROW(r0 - 2, xb);
        COMPUTE_DD(r0 - 2, d1x, d1y, d1z);
        COMPUTE_DD(r0 - 1, cx, cy, cz);
#pragma unroll
        for (int i=0;i<8;i++){ p2x[i]=d1x[i]+cx[i]; p2y[i]=d1y[i]+cy[i]; p2z[i]=d1z[i]+cz[i]; }
        pstart = r0 - 1;
    }

    const int pend = (r1 == HH) ? (HH - 1) : (r1 + 1);
#pragma unroll 2
    for (int p = pstart; p < pend; ++p) {
        float nx[8], ny[8], nz[8];
        COMPUTE_DD(p+1, nx, ny, nz);
        float sxx[8], sxy[8], syy[8];
#pragma unroll
        for (int i=0;i<8;i++){ sxx[i]=p2x[i]+nx[i];
                               sxy[i]=p2y[i]+ny[i];
                               syy[i]=p2z[i]+nz[i]; }
#pragma unroll
        for (int i=0;i<8;i++){ p2x[i]=cx[i]+nx[i]; cx[i]=nx[i];
                               p2y[i]=cy[i]+ny[i]; cy[i]=ny[i];
                               p2z[i]=cz[i]+nz[i]; cz[i]=nz[i]; }
        EMIT_P(p);
    }

    if (r1 == HH) {
        // peel p = 255: vertical sum = dd(255) + 2*(p2-dd(255)) (= +2*dd(254))
        float sxx[8], sxy[8], syy[8];
#pragma unroll
        for (int i=0;i<8;i++){
            sxx[i] = fmaf(2.0f, p2x[i] - cx[i], cx[i]);
            sxy[i] = fmaf(2.0f, p2y[i] - cy[i], cy[i]);
            syy[i] = fmaf(2.0f, p2z[i] - cz[i], cz[i]);
        }
        EMIT_P(255);
        // bottom image row: chunkmax(255) = max(h(254), h(255))
        float cm = fmaxf(hb, ha);
        lmax = fmaxf(lmax, cm);
        g_cmax32[((img<<8)+(HH-1))*32 + lane] = cm;
    }

#pragma unroll
    for (int o=16;o;o>>=1) lmax = fmaxf(lmax, __shfl_xor_sync(0xffffffffu, lmax, o));
    if (lane == 0) g_segmax[img * NSEG + seg] = lmax;
}

// ---------------------------------------------------------------------------
// Scan: compute t per image, compact flagged chunks (cmax >= t) into g_list
// with warp-aggregated atomics. Each thread covers 2 chunks via one float4.
// Grid: 4096 blocks x 256 (8 blocks per image).
// ---------------------------------------------------------------------------
__global__ void scan_kernel() {
    __shared__ float s16[16];
    const int img = blockIdx.x >> 3;
    if (threadIdx.x < 16) s16[threadIdx.x] = g_segmax[img * NSEG + threadIdx.x];
    __syncthreads();
    float m = s16[0];
#pragma unroll
    for (int i=1;i<16;i++) m = fmaxf(m, s16[i]);
    const float t = 0.7f * m;   // THRESH_FRAC
    if ((blockIdx.x & 7) == 0 && threadIdx.x == 0) g_tmax[img] = t;

    int pair = blockIdx.x * 256 + threadIdx.x;      // 2 chunks per thread
    float4 v = *reinterpret_cast<const float4*>(g_cmax32 + (size_t)pair * 4);
    int cid0 = pair * 2;
    bool f0 = fmaxf(v.x, v.y) >= t;
    bool f1 = fmaxf(v.z, v.w) >= t;

    unsigned b0 = __ballot_sync(0xffffffffu, f0);
    unsigned b1 = __ballot_sync(0xffffffffu, f1);
    int n0 = __popc(b0);
    int tot = n0 + __popc(b1);
    if (tot) {
        int lane = threadIdx.x & 31;
        unsigned lt = (1u << lane) - 1u;
        int basep = 0;
        if (lane == 0) basep = atomicAdd(&g_count, tot);
        basep = __shfl_sync(0xffffffffu, basep, 0);
        if (f0) g_list[basep + __popc(b0 & lt)] = cid0;
        if (f1) g_list[basep + n0 + __popc(b1 & lt)] = cid0 + 1;
    }
}

// ---------------------------------------------------------------------------
// Apply: 16K warps grid-stride the compacted list. One warp per flagged
// chunk: 21 upfront parallel x loads, recompute dst bit-identical to pass A,
// then conv1x1 for flagged pixels in groups of 4 (8 batched loads -> one
// latency wait per group instead of per pixel), overwrite out.
// ---------------------------------------------------------------------------
__global__ void apply_kernel(const float* __restrict__ x, const float* __restrict__ wt,
                             const float* __restrict__ bias, float* __restrict__ out) {
    const int gwarp  = (blockIdx.x * blockDim.x + threadIdx.x) >> 5;
    const int nwarps = (gridDim.x * blockDim.x) >> 5;
    const int lane = threadIdx.x & 31;
    const float SC = (1.0f / 12.0f);
    const int total = g_count;

    for (int li = gwarp; li < total; li += nwarps) {
        int cid = g_list[li];
        int img = cid >> 12;
        int rc  = cid & 4095;
        int q   = rc >> 4;
        int c0  = (rc & 15) << 4;
        float t = g_tmax[img];
        const float* __restrict__ xim = x + (size_t)img * HWSZ;

        int c  = c0 - 2 + lane;                 // field column
        int cc = (c < 0) ? -c : (c >= WW ? 2*WW - 2 - c : c);
        int cL = (cc == 0) ? 1 : cc - 1;        // reflect-101 col for x loads
        int cR = (cc == WW-1) ? WW-2 : cc + 1;

        int dlo = q - 2 < 0 ? 0 : q - 2;

        // Upfront parallel loads: 7 rows x 3 cols (independent -> MLP 21).
        float xr0[7], xr1[7], xr2[7];
#pragma unroll
        for (int j = 0; j < 7; ++j) {
            int rj = rrow(dlo - 1 + j) * WW;
            xr0[j] = xim[rj + cL];
            xr1[j] = xim[rj + cc];
            xr2[j] = xim[rj + cR];
        }
        float xq = xim[q * WW + cc];            // x at (q, cc) for the mask

        float ddx[5], ddxy[5], ddy2[5];
#pragma unroll
        for (int k = 0; k < 5; ++k) {           // d = dlo + k (k>span unused)
            float uL = fmaf(2.0f, xr0[k+1], xr0[k]) + xr0[k+2];
            float uR = fmaf(2.0f, xr2[k+1], xr2[k]) + xr2[k+2];
            float vL = xr0[k+2] - xr0[k];
            float vC = xr1[k+2] - xr1[k];
            float vR = xr2[k+2] - xr2[k];
            float dx = (uR - uL) * SC;
            float dy = (fmaf(2.0f, vC, vL) + vR) * SC;
            ddx[k]  = dx * dx;
            ddxy[k] = dx * dy;
            ddy2[k] = dy * dy;
        }

        float dstv = -CUDART_INF_F;
        for (int rr = q - 1; rr <= q + 1; ++rr) {
            if (rr < 0 || rr > HH - 1) continue;
            float sxx, sxy, syy;
            if (rr == 0) {
                sxx = fmaf(2.0f, ddx[CL(1 - dlo)],  ddx[CL(0 - dlo)]);
                sxy = fmaf(2.0f, ddxy[CL(1 - dlo)], ddxy[CL(0 - dlo)]);
                syy = fmaf(2.0f, ddy2[CL(1 - dlo)], ddy2[CL(0 - dlo)]);
            } else if (rr == HH - 1) {
                float p2a = ddx[CL(254 - dlo)]  + ddx[CL(255 - dlo)];
                float p2b = ddxy[CL(254 - dlo)] + ddxy[CL(255 - dlo)];
                float p2c = ddy2[CL(254 - dlo)] + ddy2[CL(255 - dlo)];
                sxx = fmaf(2.0f, p2a - ddx[CL(255 - dlo)],  ddx[CL(255 - dlo)]);
                sxy = fmaf(2.0f, p2b - ddxy[CL(255 - dlo)], ddxy[CL(255 - dlo)]);
                syy = fmaf(2.0f, p2c - ddy2[CL(255 - dlo)], ddy2[CL(255 - dlo)]);
            } else {
                sxx = (ddx[CL(rr - 1 - dlo)]  + ddx[CL(rr - dlo)])  + ddx[CL(rr + 1 - dlo)];
                sxy = (ddxy[CL(rr - 1 - dlo)] + ddxy[CL(rr - dlo)]) + ddxy[CL(rr + 1 - dlo)];
                syy = (ddy2[CL(rr - 1 - dlo)] + ddy2[CL(rr - dlo)]) + ddy2[CL(rr + 1 - dlo)];
            }
            float xxm = __shfl_up_sync(0xffffffffu, sxx, 1);
            float xxp = __shfl_down_sync(0xffffffffu, sxx, 1);
            float xym = __shfl_up_sync(0xffffffffu, sxy, 1);
            float xyp = __shfl_down_sync(0xffffffffu, sxy, 1);
            float yym = __shfl_up_sync(0xffffffffu, syy, 1);
            float yyp = __shfl_down_sync(0xffffffffu, syy, 1);
            float ixx = (xxm + sxx) + xxp;
            float ixy = (xym + sxy) + xyp;
            float iyy = (yym + syy) + yyp;
            float t1 = ixy * ixy;
            float det = fmaf(ixx, iyy, -t1);
            float tr  = ixx + iyy;
            float t2 = tr * tr;
            float Rv = fmaf(-0.04f, t2, det);
            if (c < 0 || c > WW - 1) Rv = -CUDART_INF_F;   // dilation clips
            float Rm = __shfl_up_sync(0xffffffffu, Rv, 1);
            float Rp = __shfl_down_sync(0xffffffffu, Rv, 1);
            float mm = fmaxf(fmaxf(Rm, Rv), Rp);
            dstv = fmaxf(dstv, mm);
        }

        bool flg = (lane >= 2) && (lane < 18) && (dstv >= t);
        unsigned bal = __ballot_sync(0xffffffffu, flg);
        if (bal) {
            int b   = img >> 6;
            int cch = img & 63;
            float w0 = wt[(cch << 6) + 2*lane];
            float w1 = wt[(cch << 6) + 2*lane + 1];
            float bi = bias[cch];
            const float* xbase = x + (size_t)(b << 6) * HWSZ;
            // Process flagged pixels in groups of 4: batch the loads (MLP 8,
            // one latency wait per group), then 4 independent reduces.
            while (bal) {
                float xv0[4], xv1[4];
                int   lps[4];
                int   cnt = 0;
#pragma unroll
                for (int k = 0; k < 4; ++k) {
                    if (bal) {
                        int lp = __ffs(bal) - 1; bal &= bal - 1;
                        lps[k] = lp;
                        int pix = (q << 8) + c0 + lp - 2;
                        xv0[k] = xbase[(size_t)(2*lane)     * HWSZ + pix];
                        xv1[k] = xbase[(size_t)(2*lane + 1) * HWSZ + pix];
                        cnt = k + 1;
                    }
                }
#pragma unroll
                for (int k = 0; k < 4; ++k) {
                    if (k < cnt) {
                        float acc = fmaf(w0, xv0[k], w1 * xv1[k]);
#pragma unroll
                        for (int o = 16; o; o >>= 1)
                            acc += __shfl_xor_sync(0xffffffffu, acc, o);
                        if (lane == lps[k]) {
                            float y = fmaxf(acc + bi, 0.0f);
                            float mask = (dstv > t) ? 1.0f : xq;   // tie keeps pixel
                            out[(size_t)img * HWSZ + ((q << 8) + c0 + lps[k] - 2)]
                                = fmaf(mask, y, xq);
                        }
                    }
                }
            }
        }
    }
}

extern "C" void kernel_launch(void* const* d_in, const int* in_sizes, int n_in,
                              void* d_out, int out_size) {
    const float* x = (const float*)d_in[0];
    const float* w = (const float*)d_in[1];
    const float* b = (const float*)d_in[2];
    float* out = (float*)d_out;
    harris_kernel<<<NIMG * NSEG, 32>>>(x, out);
    scan_kernel<<<4096, 256>>>();
    apply_kernel<<<2048, 256>>>(x, w, b, out);
}

// round 10
// speedup vs baseline: 1.3378x; 1.0195x over previous
#include <cuda_runtime.h>
#include <math_constants.h>

#define HH 256
#define WW 256
#define NIMG 512          // B*C = 8*64
#define CCH 64
#define HWSZ 65536        // 256*256
#define NSEG 14           // segments per image (4x19 + 10x18 rows)

// Scratch (static device globals — no runtime allocation)
__device__ float g_cmax32[NIMG * HH * 32];    // per-(row, lane=8col) max of dst
__device__ float g_segmax[NIMG * NSEG];       // per-segment max of dst

__device__ __forceinline__ int rrow(int r) {
    return r < 0 ? -r : (r >= HH ? 2*HH - 2 - r : r);
}

// clamp dynamic local-array index into [0,4] — prevents speculative
// out-of-frame LDL when ptxas flattens the border branches into selects
#define CL(i) (min(max((int)(i), 0), 4))

// ---------------------------------------------------------------------------
// Pass A: Harris response R -> per-lane chunk maxes of the 3x3-dilated field
// (dst itself never materialized), segment maxes, out=x copy fused into the
// stencil row loads. One warp per (image, segment); lane owns 8 cols.
// All FP contractions pinned with explicit fmaf so the apply path can
// recompute dst bit-identically.
// ---------------------------------------------------------------------------

// Load x row r (reflect-101). If the REQUESTED row lies in this segment,
// also store it to out (each segment row passes through here exactly once).
#define LOAD_XROW(r, dst_)  do {                                              \
    int rq__ = (r);                                                           \
    int rr__ = (rq__ < 0) ? -rq__ : ((rq__ >= HH) ? (2*HH - 2 - rq__) : rq__);\
    const float4* p__ = reinterpret_cast<const float4*>(xim + rr__ * WW + cb);\
    float4 q0__ = p__[0], q1__ = p__[1];                                      \
    dst_[0]=q0__.x; dst_[1]=q0__.y; dst_[2]=q0__.z; dst_[3]=q0__.w;           \
    dst_[4]=q1__.x; dst_[5]=q1__.y; dst_[6]=q1__.z; dst_[7]=q1__.w;           \
    if ((unsigned)(rq__ - r0) < (unsigned)seglen) {                           \
        float4* po__ = reinterpret_cast<float4*>(oim + rq__ * WW + cb);       \
        po__[0] = q0__; po__[1] = q1__;                                       \
    }                                                                         \
} while(0)

#define COMPUTE_DD(row, AX, AXY, AY) do {                                     \
    float xc__[8]; LOAD_XROW((row)+1, xc__);                                  \
    float u__[8], v__[8];                                                     \
    _Pragma("unroll")                                                         \
    for (int i=0;i<8;i++){ u__[i] = fmaf(2.0f, xb[i], xa[i]) + xc__[i];       \
                           v__[i] = xc__[i] - xa[i]; }                        \
    float uL__ = __shfl_up_sync(0xffffffffu, u__[7], 1);                      \
    float uR__ = __shfl_down_sync(0xffffffffu, u__[0], 1);                    \
    float vL__ = __shfl_up_sync(0xffffffffu, v__[7], 1);                      \
    float vR__ = __shfl_down_sync(0xffffffffu, v__[0], 1);                    \
    if (lane == 0)  { uL__ = u__[1]; vL__ = v__[1]; }                         \
    if (lane == 31) { uR__ = u__[6]; vR__ = v__[6]; }                         \
    _Pragma("unroll")                                                         \
    for (int i=0;i<8;i++){                                                    \
        float um1__ = (i==0)? uL__ : u__[i-1];                                \
        float up1__ = (i==7)? uR__ : u__[i+1];                                \
        float vm1__ = (i==0)? vL__ : v__[i-1];                                \
        float vp1__ = (i==7)? vR__ : v__[i+1];                                \
        float dx__ = (up1__ - um1__) * SC;                                    \
        float dy__ = (fmaf(2.0f, v__[i], vm1__) + vp1__) * SC;                \
        AX[i] = dx__*dx__; AXY[i] = dx__*dy__; AY[i] = dy__*dy__;             \
    }                                                                         \
    _Pragma("unroll")                                                         \
    for (int i=0;i<8;i++){ xa[i] = xb[i]; xb[i] = xc__[i]; }                  \
} while(0)

// Horizontal sums + R + per-lane row max h + emit chunkmax row q = PV-1.
#define EMIT_P(PV) do {                                                       \
    float xxL__ = __shfl_up_sync(0xffffffffu, sxx[7],1);                      \
    float xxR__ = __shfl_down_sync(0xffffffffu, sxx[0],1);                    \
    float xyL__ = __shfl_up_sync(0xffffffffu, sxy[7],1);                      \
    float xyR__ = __shfl_down_sync(0xffffffffu, sxy[0],1);                    \
    float yyL__ = __shfl_up_sync(0xffffffffu, syy[7],1);                      \
    float yyR__ = __shfl_down_sync(0xffffffffu, syy[0],1);                    \
    if (lane==0){  xxL__=sxx[1]; xyL__=sxy[1]; yyL__=syy[1]; }                \
    if (lane==31){ xxR__=sxx[6]; xyR__=sxy[6]; yyR__=syy[6]; }                \
    float Rv__[8];                                                            \
    _Pragma("unroll")                                                         \
    for (int i=0;i<8;i++){                                                    \
        float ixx = (((i==0)?xxL__:sxx[i-1]) + sxx[i]) + ((i==7)?xxR__:sxx[i+1]);\
        float ixy = (((i==0)?xyL__:sxy[i-1]) + sxy[i]) + ((i==7)?xyR__:sxy[i+1]);\
        float iyy = (((i==0)?yyL__:syy[i-1]) + syy[i]) + ((i==7)?yyR__:syy[i+1]);\
        float t1__ = ixy * ixy;                                               \
        float det__ = fmaf(ixx, iyy, -t1__);                                  \
        float tr__  = ixx + iyy;                                              \
        float t2__ = tr__ * tr__;                                             \
        Rv__[i] = fmaf(-0.04f, t2__, det__);                                  \
    }                                                                         \
    float RL__ = __shfl_up_sync(0xffffffffu, Rv__[7],1);                      \
    float RR__ = __shfl_down_sync(0xffffffffu, Rv__[0],1);                    \
    if (lane==0)  RL__ = -CUDART_INF_F;                                       \
    if (lane==31) RR__ = -CUDART_INF_F;                                       \
    float hc__ = fmaxf(RL__, RR__);                                           \
    _Pragma("unroll")                                                         \
    for (int i=0;i<8;i++) hc__ = fmaxf(hc__, Rv__[i]);                        \
    int q__ = (PV) - 1;                                                       \
    if (q__ >= r0) {                                                          \
        float cm__ = fmaxf(fmaxf(hb, ha), hc__);                              \
        lmax = fmaxf(lmax, cm__);                                             \
        g_cmax32[((img<<8)+q__)*32 + lane] = cm__;                            \
    }                                                                         \
    hb = ha; ha = hc__;                                                       \
} while(0)

__global__ void __launch_bounds__(32, 16) harris_kernel(const float* __restrict__ x,
                                                        float* __restrict__ out) {
    const int img  = blockIdx.x / NSEG;
    const int seg  = blockIdx.x - img * NSEG;
    const int lane = threadIdx.x;
    const int cb   = lane * 8;
    const float* __restrict__ xim = x + (size_t)img * HWSZ;
    float* __restrict__ oim = out + (size_t)img * HWSZ;

    // 4 segments of 19 rows then 10 of 18 rows (total 256); grid 7168 warps
    // = 3.03 waves at 16 resident blocks/SM (kills wave quantization).
    const int r0     = seg * 18 + min(seg, 4);
    const int seglen = 18 + (seg < 4 ? 1 : 0);
    const int r1     = r0 + seglen;

    const float SC = (1.0f / 12.0f);   // SOBEL_SCALE
    float xa[8], xb[8];
    float p2x[8], p2y[8], p2z[8];      // P2 = dd(p-1)+dd(p)   (xx,xy,yy)
    float cx[8],  cy[8],  cz[8];       // C  = dd(p)
    float ha = -CUDART_INF_F, hb = -CUDART_INF_F;  // h(p-1), h(p-2)
    float lmax = -CUDART_INF_F;

    int pstart;
    if (r0 == 0) {
        LOAD_XROW(-1, xa);
        LOAD_XROW(0,  xb);
        COMPUTE_DD(0, cx, cy, cz);
#pragma unroll
        for (int i=0;i<8;i++){ p2x[i]=cx[i]+cx[i]; p2y[i]=cy[i]+cy[i]; p2z[i]=cz[i]+cz[i]; }
        // peeled p == 0 iteration (emits q=-1: nothing; shifts ha/hb)
        {
            float nx[8], ny[8], nz[8];
            COMPUTE_DD(1, nx, ny, nz);
            float sxx[8], sxy[8], syy[8];
#pragma unroll
            for (int i=0;i<8;i++){ sxx[i]=fmaf(2.0f, nx[i], cx[i]);
                                   sxy[i]=fmaf(2.0f, ny[i], cy[i]);
                                   syy[i]=fmaf(2.0f, nz[i], cz[i]); }
#pragma unroll
            for (int i=0;i<8;i++){ p2x[i]=cx[i]+nx[i]; cx[i]=nx[i];
                                   p2y[i]=cy[i]+ny[i]; cy[i]=ny[i];
                                   p2z[i]=cz[i]+nz[i]; cz[i]=nz[i]; }
            EMIT_P(0);
        }
        pstart = 1;
    } else {
        float d1x[8], d1y[8], d1z[8];
        LOAD_XROW(r0 - 3, xa);
        LOAD_XROW(r0 - 2, xb);
        COMPUTE_DD(r0 - 2, d1x, d1y, d1z);
        COMPUTE_DD(r0 - 1, cx, cy, cz);
#pragma unroll
        for (int i=0;i<8;i++){ p2x[i]=d1x[i]+cx[i]; p2y[i]=d1y[i]+cy[i]; p2z[i]=d1z[i]+cz[i]; }
        pstart = r0 - 1;
    }

    const int pend = (r1 == HH) ? (HH - 1) : (r1 + 1);
#pragma unroll 2
    for (int p = pstart; p < pend; ++p) {
        float nx[8], ny[8], nz[8];
        COMPUTE_DD(p+1, nx, ny, nz);
        float sxx[8], sxy[8], syy[8];
#pragma unroll
        for (int i=0;i<8;i++){ sxx[i]=p2x[i]+nx[i];
                               sxy[i]=p2y[i]+ny[i];
                               syy[i]=p2z[i]+nz[i]; }
#pragma unroll
        for (int i=0;i<8;i++){ p2x[i]=cx[i]+nx[i]; cx[i]=nx[i];
                               p2y[i]=cy[i]+ny[i]; cy[i]=ny[i];
                               p2z[i]=cz[i]+nz[i]; cz[i]=nz[i]; }
        EMIT_P(p);
    }

    if (r1 == HH) {
        // peel p = 255: vertical sum = dd(255) + 2*(p2-dd(255)) (= +2*dd(254))
        float sxx[8], sxy[8], syy[8];
#pragma unroll
        for (int i=0;i<8;i++){
            sxx[i] = fmaf(2.0f, p2x[i] - cx[i], cx[i]);
            sxy[i] = fmaf(2.0f, p2y[i] - cy[i], cy[i]);
            syy[i] = fmaf(2.0f, p2z[i] - cz[i], cz[i]);
        }
        EMIT_P(255);
        // bottom image row: chunkmax(255) = max(h(254), h(255))
        float cm = fmaxf(hb, ha);
        lmax = fmaxf(lmax, cm);
        g_cmax32[((img<<8)+(HH-1))*32 + lane] = cm;
    }

#pragma unroll
    for (int o=16;o;o>>=1) lmax = fmaxf(lmax, __shfl_xor_sync(0xffffffffu, lmax, o));
    if (lane == 0) g_segmax[img * NSEG + seg] = lmax;
}

// ---------------------------------------------------------------------------
// Detect + apply (fused, balanced): 4096 blocks x 256 threads; block covers
// 512 contiguous chunks (32 rows of one image). Both loads (cmax float4 +
// segmax) are issued BEFORE the sync so there is a single latency window.
// Flagged chunks go to a block-smem list; the block's 8 warps redistribute
// them (a 3-6 chunk corner cluster spreads across warps instead of
// serializing). Apply: recompute dst bit-identical to pass A, then conv1x1
// with batched loads for flagged pixels; overwrite out.
// ---------------------------------------------------------------------------
__global__ void __launch_bounds__(256) detect_apply_kernel(
        const float* __restrict__ x, const float* __restrict__ wt,
        const float* __restrict__ bias, float* __restrict__ out) {
    __shared__ float s14[NSEG];
    __shared__ int   slist[512];
    __shared__ int   scount;
    const int img   = blockIdx.x >> 3;
    const int tid   = threadIdx.x;

    // both global loads in flight before the sync
    const float4 v = *reinterpret_cast<const float4*>(
        g_cmax32 + ((size_t)blockIdx.x << 10) + (tid << 2));
    if (tid == 0) scount = 0;
    if (tid < NSEG) s14[tid] = g_segmax[img * NSEG + tid];
    __syncthreads();

    float m = s14[0];
#pragma unroll
    for (int i = 1; i < NSEG; i++) m = fmaxf(m, s14[i]);
    const float thr = 0.7f * m;   // THRESH_FRAC * image max

    // local chunk ids within image: this thread's float4 covers chunks lc, lc+1
    const int lc = (((blockIdx.x & 7) << 8) + tid) << 1;
    if (fmaxf(v.x, v.y) >= thr) slist[atomicAdd(&scount, 1)] = lc;
    if (fmaxf(v.z, v.w) >= thr) slist[atomicAdd(&scount, 1)] = lc + 1;
    __syncthreads();
    const int n = scount;
    if (n == 0) return;

    const int wid  = tid >> 5;
    const int lane = tid & 31;
    const float SC = (1.0f / 12.0f);
    const float* __restrict__ xim = x + (size_t)img * HWSZ;

    for (int li = wid; li < n; li += 8) {
        int rc  = slist[li];
        int q   = rc >> 4;
        int c0  = (rc & 15) << 4;

        int c  = c0 - 2 + lane;                 // field column
        int cc = (c < 0) ? -c : (c >= WW ? 2*WW - 2 - c : c);
        int cL = (cc == 0) ? 1 : cc - 1;        // reflect-101 col for x loads
        int cR = (cc == WW-1) ? WW-2 : cc + 1;

        int dlo = q - 2 < 0 ? 0 : q - 2;

        // Upfront parallel loads: 7 rows x 3 cols (independent -> MLP 21).
        float xr0[7], xr1[7], xr2[7];
#pragma unroll
        for (int j = 0; j < 7; ++j) {
            int rj = rrow(dlo - 1 + j) * WW;
            xr0[j] = xim[rj + cL];
            xr1[j] = xim[rj + cc];
            xr2[j] = xim[rj + cR];
        }
        float xq = xim[q * WW + cc];            // x at (q, cc) for the mask

        float ddx[5], ddxy[5], ddy2[5];
#pragma unroll
        for (int k = 0; k < 5; ++k) {           // d = dlo + k (k>span unused)
            float uL = fmaf(2.0f, xr0[k+1], xr0[k]) + xr0[k+2];
            float uR = fmaf(2.0f, xr2[k+1], xr2[k]) + xr2[k+2];
            float vL = xr0[k+2] - xr0[k];
            float vC = xr1[k+2] - xr1[k];
            float vR = xr2[k+2] - xr2[k];
            float dx = (uR - uL) * SC;
            float dy = (fmaf(2.0f, vC, vL) + vR) * SC;
            ddx[k]  = dx * dx;
            ddxy[k] = dx * dy;
            ddy2[k] = dy * dy;
        }

        float dstv = -CUDART_INF_F;
        for (int rr = q - 1; rr <= q + 1; ++rr) {
            if (rr < 0 || rr > HH - 1) continue;
            float sxx, sxy, syy;
            if (rr == 0) {
                sxx = fmaf(2.0f, ddx[CL(1 - dlo)],  ddx[CL(0 - dlo)]);
                sxy = fmaf(2.0f, ddxy[CL(1 - dlo)], ddxy[CL(0 - dlo)]);
                syy = fmaf(2.0f, ddy2[CL(1 - dlo)], ddy2[CL(0 - dlo)]);
            } else if (rr == HH - 1) {
                float p2a = ddx[CL(254 - dlo)]  + ddx[CL(255 - dlo)];
                float p2b = ddxy[CL(254 - dlo)] + ddxy[CL(255 - dlo)];
                float p2c = ddy2[CL(254 - dlo)] + ddy2[CL(255 - dlo)];
                sxx = fmaf(2.0f, p2a - ddx[CL(255 - dlo)],  ddx[CL(255 - dlo)]);
                sxy = fmaf(2.0f, p2b - ddxy[CL(255 - dlo)], ddxy[CL(255 - dlo)]);
                syy = fmaf(2.0f, p2c - ddy2[CL(255 - dlo)], ddy2[CL(255 - dlo)]);
            } else {
                sxx = (ddx[CL(rr - 1 - dlo)]  + ddx[CL(rr - dlo)])  + ddx[CL(rr + 1 - dlo)];
                sxy = (ddxy[CL(rr - 1 - dlo)] + ddxy[CL(rr - dlo)]) + ddxy[CL(rr + 1 - dlo)];
                syy = (ddy2[CL(rr - 1 - dlo)] + ddy2[CL(rr - dlo)]) + ddy2[CL(rr + 1 - dlo)];
            }
            float xxm = __shfl_up_sync(0xffffffffu, sxx, 1);
            float xxp = __shfl_down_sync(0xffffffffu, sxx, 1);
            float xym = __shfl_up_sync(0xffffffffu, sxy, 1);
            float xyp = __shfl_down_sync(0xffffffffu, sxy, 1);
            float yym = __shfl_up_sync(0xffffffffu, syy, 1);
            float yyp = __shfl_down_sync(0xffffffffu, syy, 1);
            float ixx = (xxm + sxx) + xxp;
            float ixy = (xym + sxy) + xyp;
            float iyy = (yym + syy) + yyp;
            float t1 = ixy * ixy;
            float det = fmaf(ixx, iyy, -t1);
            float tr  = ixx + iyy;
            float t2 = tr * tr;
            float Rv = fmaf(-0.04f, t2, det);
            if (c < 0 || c > WW - 1) Rv = -CUDART_INF_F;   // dilation clips
            float Rm = __shfl_up_sync(0xffffffffu, Rv, 1);
            float Rp = __shfl_down_sync(0xffffffffu, Rv, 1);
            float mm = fmaxf(fmaxf(Rm, Rv), Rp);
            dstv = fmaxf(dstv, mm);
        }

        bool flg = (lane >= 2) && (lane < 18) && (dstv >= thr);
        unsigned bal = __ballot_sync(0xffffffffu, flg);
        if (bal) {
            int b   = img >> 6;
            int cch = img & 63;
            float w0 = wt[(cch << 6) + 2*lane];
            float w1 = wt[(cch << 6) + 2*lane + 1];
            float bi = bias[cch];
            const float* xbase = x + (size_t)(b << 6) * HWSZ;
            // Process flagged pixels in groups of 4: batch the loads (MLP 8,
            // one latency wait per group), then 4 independent reduces.
            while (bal) {
                float xv0[4], xv1[4];
                int   lps[4];
                int   cnt = 0;
#pragma unroll
                for (int k = 0; k < 4; ++k) {
                    if (bal) {
                        int lp = __ffs(bal) - 1; bal &= bal - 1;
                        lps[k] = lp;
                        int pix = (q << 8) + c0 + lp - 2;
                        xv0[k] = xbase[(size_t)(2*lane)     * HWSZ + pix];
                        xv1[k] = xbase[(size_t)(2*lane + 1) * HWSZ + pix];
                        cnt = k + 1;
                    }
                }
#pragma unroll
                for (int k = 0; k < 4; ++k) {
                    if (k < cnt) {
                        float acc = fmaf(w0, xv0[k], w1 * xv1[k]);
#pragma unroll
                        for (int o = 16; o; o >>= 1)
                            acc += __shfl_xor_sync(0xffffffffu, acc, o);
                        if (lane == lps[k]) {
                            float y = fmaxf(acc + bi, 0.0f);
                            float mask = (dstv > thr) ? 1.0f : xq;   // tie keeps pixel
                            out[(size_t)img * HWSZ + ((q << 8) + c0 + lps[k] - 2)]
                                = fmaf(mask, y, xq);
                        }
                    }
                }
            }
        }
    }
}

extern "C" void kernel_launch(void* const* d_in, const int* in_sizes, int n_in,
                              void* d_out, int out_size) {
    const float* x = (const float*)d_in[0];
    const float* w = (const float*)d_in[1];
    const float* b = (const float*)d_in[2];
    float* out = (float*)d_out;
    harris_kernel<<<NIMG * NSEG, 32>>>(x, out);
    detect_apply_kernel<<<NIMG * 8, 256>>>(x, w, b, out);
}